// round 14
// baseline (speedup 1.0000x reference)
#include <cuda_runtime.h>
#include <cuda_fp16.h>
#include <cstdint>

#define N_ 20000
#define T_ 6890
#define F_ 128
#define KTOP 6
#define KD 3                          /* per-thread packed-key list depth */
#define KCH 6                         /* per (row,chunk) output depth (exact top-6) */
#define DEG 32
#define QSPLIT 8
#define RTILES 157                    /* ceil(20000/128) */
#define NROWPAD (RTILES * 128)        /* 20096 */
#define CTILES 54                     /* ceil(6890/128) */
#define CTILEPAD (CTILES * 128)       /* 6912 */
#define VBIG 384.0f

// ---------------- device scratch ----------------
__device__ __align__(128) unsigned char g_Shi[NROWPAD * 256];   // fp16 [row][128]
__device__ __align__(128) unsigned char g_Thi[CTILEPAD * 256];  // fp16 [col][128]
__device__ __align__(128) float g_tnT[CTILEPAD];                // exact ||t||^2 (+inf pad)
__device__ __align__(128) float g_tnB[CTILEPAD];                // 384 - ||t||^2 (1e-20 pad)
__device__ uint32_t g_partK[N_ * QSPLIT * KCH];                 // packed keys
__device__ __align__(128) float g_pp[N_ * 6];                   // [pos3 | pred3] per node
__device__ float g_pm[N_ * 9];
__device__ float g_srcc[N_ * 3];
__device__ float g_tgtc[N_ * 3];
__device__ float g_res[N_];                                     // per-node residual magnitude^2

// ---------------- smem offsets (phase-1 kernel, triple-buffered B) ----------------
#define OFF_A    0                      /* 2 panels x 16KB = 32KB */
#define OFF_B(s) (32768 + (s) * 32768)  /* 3 stages x (2 panels x 16KB) */
#define OFF_TN   163840                 /* 7*128 floats = 3584B */
#define OFF_MRG  167424                 /* 128 rows x 24 keys = 12KB */
#define MAIN_SMEM 179712

// ---------------- helpers ----------------
__device__ __forceinline__ uint32_t smem_u32(const void* p) {
    uint32_t a;
    asm("{ .reg .u64 t; cvta.to.shared.u64 t, %1; cvt.u32.u64 %0, t; }" : "=r"(a) : "l"(p));
    return a;
}
__device__ __forceinline__ uint32_t sw(uint32_t x) { return x ^ ((x >> 3) & 0x70); }

__device__ __forceinline__ void cp_async16(uint32_t dst, const void* src) {
    asm volatile("cp.async.cg.shared.global [%0], [%1], 16;" :: "r"(dst), "l"(src));
}
__device__ __forceinline__ void cp_commit() { asm volatile("cp.async.commit_group;"); }
__device__ __forceinline__ void cp_wait1()  { asm volatile("cp.async.wait_group 1;"); }

__device__ __forceinline__ void ldsm4(uint32_t (&r)[4], uint32_t addr) {
    asm volatile("ldmatrix.sync.aligned.m8n8.x4.shared.b16 {%0,%1,%2,%3}, [%4];"
                 : "=r"(r[0]), "=r"(r[1]), "=r"(r[2]), "=r"(r[3]) : "r"(addr));
}
__device__ __forceinline__ void mma16816(float (&d)[4], const uint32_t (&a)[4], const uint32_t b0, const uint32_t b1) {
    asm volatile(
        "mma.sync.aligned.m16n8k16.row.col.f32.f16.f16.f32 "
        "{%0,%1,%2,%3}, {%4,%5,%6,%7}, {%8,%9}, {%0,%1,%2,%3};"
        : "+f"(d[0]), "+f"(d[1]), "+f"(d[2]), "+f"(d[3])
        : "r"(a[0]), "r"(a[1]), "r"(a[2]), "r"(a[3]), "r"(b0), "r"(b1));
}

// positive-float key: raw bits (order-isomorphic for v>0), low 13 bits = column index
__device__ __forceinline__ uint32_t pos_key(float v, int idx) {
    return (__float_as_uint(v) & 0xFFFFE000u) | (uint32_t)idx;
}

// branchless sorted-insert via IMNMX pairs
template <int K>
__device__ __forceinline__ void insKey(uint32_t k, uint32_t (&L)[K]) {
#pragma unroll
    for (int q = 0; q < K; q++) {
        uint32_t mx = max(L[q], k);
        k = min(L[q], k);
        L[q] = mx;
    }
}

template <int K>
__device__ __forceinline__ void insertK(float v, int idx, float (&tv)[K], int (&ti)[K]) {
    if (v <= tv[K - 1]) return;
    float cv = v; int ci = idx;
#pragma unroll
    for (int q = 0; q < K; q++) {
        if (cv > tv[q]) {
            float t1 = tv[q]; int t2 = ti[q];
            tv[q] = cv; ti[q] = ci;
            cv = t1; ci = t2;
        }
    }
}

// ---------------- convert kernels ----------------
__global__ void convS_kernel(const float* __restrict__ S, const float* __restrict__ pos) {
    int idx = blockIdx.x * blockDim.x + threadIdx.x;
    if (idx >= NROWPAD * F_) return;
    int n = idx >> 7, k = idx & 127;
    float x = (n < N_) ? S[(size_t)n * F_ + k] : 0.f;
    *reinterpret_cast<__half*>(g_Shi + (size_t)n * 256 + k * 2) = __float2half_rn(x);
    if (idx < N_ * 3) {
        int nn = idx / 3, j = idx - nn * 3;
        g_pp[nn * 6 + j] = pos[idx];
    }
}

// fused: fp16 convert of T + exact tn + shifted tnB (warp per target row)
__global__ void convT_tn_kernel(const float* __restrict__ Tf) {
    int c = (blockIdx.x * blockDim.x + threadIdx.x) >> 5;
    int lane = threadIdx.x & 31;
    if (c >= CTILEPAD) return;
    if (c >= T_) {
        reinterpret_cast<uint2*>(g_Thi + (size_t)c * 256)[lane] = make_uint2(0u, 0u);
        if (lane == 0) { g_tnT[c] = __int_as_float(0x7f800000); g_tnB[c] = 1e-20f; }
        return;
    }
    float4 v = reinterpret_cast<const float4*>(Tf + (size_t)c * F_)[lane];
    float s = v.x * v.x + v.y * v.y + v.z * v.z + v.w * v.w;
#pragma unroll
    for (int o = 16; o; o >>= 1) s += __shfl_xor_sync(0xffffffffu, s, o);
    __half2 h0 = __floats2half2_rn(v.x, v.y);
    __half2 h1 = __floats2half2_rn(v.z, v.w);
    uint2 pack;
    pack.x = *reinterpret_cast<uint32_t*>(&h0);
    pack.y = *reinterpret_cast<uint32_t*>(&h1);
    reinterpret_cast<uint2*>(g_Thi + (size_t)c * 256)[lane] = pack;
    if (lane == 0) { g_tnT[c] = s; g_tnB[c] = VBIG - s; }
}

// ---------------- phase 1: fp16 GEMM + packed-key approx selection ----------------
// warp grid 8(wm) x 2(wn): warp tile 16 rows x 64 cols; thread holds rows ra, ra+8
__device__ __forceinline__ void load_B(uint32_t sb, int stage, int ct, int tid) {
#pragma unroll
    for (int j = 0; j < 4; j++) {
        int id = tid + j * 512;
        int p = id >> 10, cid = id & 1023;
        int row = cid >> 3, cc = (cid & 7) * 16;
        cp_async16(sb + OFF_B(stage) + p * 16384 + sw(row * 128 + cc),
                   g_Thi + (size_t)(ct * 128 + row) * 256 + p * 128 + cc);
    }
}

__global__ __launch_bounds__(512, 1) void mma_topk_kernel() {
    extern __shared__ __align__(1024) unsigned char smem[];
    const uint32_t sb = smem_u32(smem);
    const float* tnS = reinterpret_cast<const float*>(smem + OFF_TN);
    uint32_t* mrg = reinterpret_cast<uint32_t*>(smem + OFF_MRG);

    const int tid  = threadIdx.x;
    const int lane = tid & 31;
    const int wid  = tid >> 5;
    const int wm   = wid >> 1;    // 0..7
    const int wn   = wid & 1;     // 0..1

    const int rblk = blockIdx.x >> 3;
    const int q    = blockIdx.x & 7;
    const int rb   = rblk * 128;
    const int t0   = (CTILES * q) / QSPLIT;
    const int t1   = (CTILES * (q + 1)) / QSPLIT;
    const int nt   = t1 - t0;

    uint32_t LA[KD], LB[KD];
#pragma unroll
    for (int k = 0; k < KD; k++) { LA[k] = 0u; LB[k] = 0u; }

    float acc[8][4];
#pragma unroll
    for (int ni = 0; ni < 8; ni++)
#pragma unroll
        for (int r = 0; r < 4; r++) acc[ni][r] = 0.f;

    // precomputed ldsm offsets
    uint32_t offA[4], offB4[4][4];
#pragma unroll
    for (int kk = 0; kk < 4; kk++)
        offA[kk] = sw((uint32_t)((wm * 16 + (lane & 15)) * 128 + kk * 32 + (lane >> 4) * 16));
#pragma unroll
    for (int nn = 0; nn < 4; nn++)
#pragma unroll
        for (int kk = 0; kk < 4; kk++)
            offB4[nn][kk] = sw((uint32_t)((wn * 64 + nn * 16 + ((lane >> 4) & 1) * 8 + (lane & 7)) * 128
                                          + kk * 32 + ((lane >> 3) & 1) * 16));

    // ---- prologue: group0 = {A, tnB, B0}; group1 = {B1} ----
#pragma unroll
    for (int j = 0; j < 4; j++) {
        int id = tid + j * 512;
        int p = id >> 10, cid = id & 1023;
        int row = cid >> 3, cc = (cid & 7) * 16;
        cp_async16(sb + OFF_A + p * 16384 + sw(row * 128 + cc),
                   g_Shi + (size_t)(rb + row) * 256 + p * 128 + cc);
    }
    if (tid < nt * 32)
        cp_async16(sb + OFF_TN + tid * 16, (const unsigned char*)(g_tnB + t0 * 128) + tid * 16);
    load_B(sb, 0, t0, tid);
    cp_commit();
    if (nt > 1) load_B(sb, 1, t0 + 1, tid);
    cp_commit();

    for (int i = 0; i < nt; i++) {
        int s = i % 3;
        cp_wait1();              // group(i) complete -> B(i) + (i==0: A,tn) ready
        __syncthreads();         // all threads done with stage being overwritten next
        if (i + 2 < nt) load_B(sb, (i + 2) % 3, t0 + i + 2, tid);
        cp_commit();

        // ---- compute: 2 k-half panels x 4 kk ----
#pragma unroll
        for (int p = 0; p < 2; p++) {
            uint32_t sa  = sb + OFF_A + p * 16384;
            uint32_t sbb = sb + OFF_B(s) + p * 16384;
#pragma unroll
            for (int kk = 0; kk < 4; kk++) {
                uint32_t b[8][2];
#pragma unroll
                for (int nn = 0; nn < 4; nn++) {
                    uint32_t bb[4];
                    ldsm4(bb, sbb + offB4[nn][kk]);
                    b[nn * 2][0] = bb[0]; b[nn * 2][1] = bb[1];
                    b[nn * 2 + 1][0] = bb[2]; b[nn * 2 + 1][1] = bb[3];
                }
                uint32_t a[4];
                ldsm4(a, sa + offA[kk]);
#pragma unroll
                for (int ni = 0; ni < 8; ni++) mma16816(acc[ni], a, b[ni][0], b[ni][1]);
            }
        }

        // ---- branchless packed-key epilogue ----
        {
            int cbg = (t0 + i) * 128;
            const float* tn = tnS + i * 128;
#pragma unroll
            for (int ni = 0; ni < 8; ni++) {
                int c0 = wn * 64 + ni * 8 + (lane & 3) * 2;
                float b0 = tn[c0], b1 = tn[c0 + 1];
                float v0 = fmaxf(fmaf(2.f, acc[ni][0], b0), 1e-20f);
                float v1 = fmaxf(fmaf(2.f, acc[ni][1], b1), 1e-20f);
                float v2 = fmaxf(fmaf(2.f, acc[ni][2], b0), 1e-20f);
                float v3 = fmaxf(fmaf(2.f, acc[ni][3], b1), 1e-20f);
                insKey<KD>(pos_key(v0, cbg + c0),     LA);
                insKey<KD>(pos_key(v1, cbg + c0 + 1), LA);
                insKey<KD>(pos_key(v2, cbg + c0),     LB);
                insKey<KD>(pos_key(v3, cbg + c0 + 1), LB);
                acc[ni][0] = acc[ni][1] = acc[ni][2] = acc[ni][3] = 0.f;
            }
        }
    }

    // ---- dump lists to smem; one thread per row builds exact chunk top-6 ----
    {
        int rowA = wm * 16 + (lane >> 2);
        int slot = wn * 12 + (lane & 3) * 3;
#pragma unroll
        for (int k = 0; k < KD; k++) {
            mrg[rowA * 24 + slot + k] = LA[k];
            mrg[(rowA + 8) * 24 + slot + k] = LB[k];
        }
    }
    __syncthreads();
    if (tid < 128) {
        uint32_t L6[KCH];
#pragma unroll
        for (int k = 0; k < KCH; k++) L6[k] = 0u;
#pragma unroll
        for (int i = 0; i < 24; i++) insKey<KCH>(mrg[tid * 24 + i], L6);
        int row = rb + tid;
        if (row < N_) {
            size_t base = ((size_t)row * QSPLIT + q) * KCH;
#pragma unroll
            for (int k = 0; k < KCH; k++) g_partK[base + k] = L6[k];
        }
    }
}

// ---------------- phase 2: merge 48 keys, parallel exact fp32 rescore ----------------
__global__ void rescore_kernel(const float* __restrict__ S, const float* __restrict__ Tf,
                               const float* __restrict__ TP) {
    int warp = (blockIdx.x * blockDim.x + threadIdx.x) >> 5;
    int lane = threadIdx.x & 31;
    if (warp >= N_) return;

    const uint32_t* K = g_partK + (size_t)warp * (QSPLIT * KCH);   // 48 keys
    uint32_t kA = K[lane];
    uint32_t kB = (lane < 16) ? K[32 + lane] : 0u;
    uint32_t hi = max(kA, kB), lo = min(kA, kB);

    uint32_t cand[8];
#pragma unroll
    for (int j = 0; j < 8; j++) {
        uint32_t m = __reduce_max_sync(0xffffffffu, hi);
        cand[j] = m;
        if (hi == m) { hi = lo; lo = 0u; }
    }

    // parallel rescore: lane-quad j handles candidate j (4 lanes x 32 k-elems)
    int j   = lane >> 2;
    int seg = lane & 3;
    int myidx = (int)(cand[j] & 8191u);
    myidx = (myidx < T_) ? myidx : (T_ - 1);
    const float4* Srow = reinterpret_cast<const float4*>(S + (size_t)warp * F_) + seg * 8;
    const float4* Trow = reinterpret_cast<const float4*>(Tf + (size_t)myidx * F_) + seg * 8;
    float d = 0.f;
#pragma unroll
    for (int r = 0; r < 8; r++) {
        float4 sv = Srow[r], tv = Trow[r];
        d = fmaf(sv.x, tv.x, d); d = fmaf(sv.y, tv.y, d);
        d = fmaf(sv.z, tv.z, d); d = fmaf(sv.w, tv.w, d);
    }
    d += __shfl_xor_sync(0xffffffffu, d, 1);
    d += __shfl_xor_sync(0xffffffffu, d, 2);
    float mysc = 2.f * d - g_tnT[myidx];

    // broadcast all 8 scores; every lane builds identical top-6
    float bv[KTOP]; int bi[KTOP];
#pragma unroll
    for (int k = 0; k < KTOP; k++) { bv[k] = __int_as_float(0xff800000); bi[k] = 0; }
#pragma unroll
    for (int k = 0; k < 8; k++) {
        float sc = __shfl_sync(0xffffffffu, mysc, k * 4);
        int idx = (int)(cand[k] & 8191u);
        idx = (idx < T_) ? idx : (T_ - 1);
        insertK<KTOP>(sc, idx, bv, bi);
    }

    if (lane == 0) {
        float m = bv[0];
        float w[KTOP], sum = 0.f;
#pragma unroll
        for (int k = 0; k < KTOP; k++) { w[k] = expf(bv[k] - m); sum += w[k]; }
        float inv = 1.f / sum;
        float px = 0.f, py = 0.f, pz = 0.f;
#pragma unroll
        for (int k = 0; k < KTOP; k++) {
            float wk = w[k] * inv;
            const float* tp = TP + (size_t)bi[k] * 3;
            px = fmaf(wk, tp[0], px);
            py = fmaf(wk, tp[1], py);
            pz = fmaf(wk, tp[2], pz);
        }
        g_pp[warp * 6 + 3] = px;
        g_pp[warp * 6 + 4] = py;
        g_pp[warp * 6 + 5] = pz;
    }
}

// ---------------- per-node centers + covariance (warp/node, packed pp gather) ----------------
__global__ void accum_kernel(const int* __restrict__ col) {
    int node = (blockIdx.x * blockDim.x + threadIdx.x) >> 5;
    int lane = threadIdx.x & 31;
    if (node >= N_) return;
    int c = col[node * DEG + lane];
    const float2* pp = reinterpret_cast<const float2*>(g_pp + (size_t)c * 6);
    float2 p0 = pp[0], p1 = pp[1], p2 = pp[2];
    float sx = p0.x, sy = p0.y, sz = p1.x;
    float tx = p1.y, ty = p2.x, tz = p2.y;
    float v[15] = { sx, sy, sz, tx, ty, tz,
                    sx * tx, sx * ty, sx * tz,
                    sy * tx, sy * ty, sy * tz,
                    sz * tx, sz * ty, sz * tz };
#pragma unroll
    for (int k = 0; k < 15; k++)
#pragma unroll
        for (int o = 16; o; o >>= 1) v[k] += __shfl_xor_sync(0xffffffffu, v[k], o);
    if (lane == 0) {
        const float invd = 1.f / (float)DEG;
        float scx = v[0] * invd, scy = v[1] * invd, scz = v[2] * invd;
        float tcx = v[3] * invd, tcy = v[4] * invd, tcz = v[5] * invd;
        g_srcc[node * 3 + 0] = scx; g_srcc[node * 3 + 1] = scy; g_srcc[node * 3 + 2] = scz;
        g_tgtc[node * 3 + 0] = tcx; g_tgtc[node * 3 + 1] = tcy; g_tgtc[node * 3 + 2] = tcz;
        float sc[3] = { scx, scy, scz };
        float tc[3] = { tcx, tcy, tcz };
#pragma unroll
        for (int i = 0; i < 3; i++)
#pragma unroll
            for (int j = 0; j < 3; j++)
                g_pm[node * 9 + 3 * i + j] = v[6 + 3 * i + j] - (float)DEG * sc[i] * tc[j];
    }
}

// ---------------- 3x3 Procrustes SVD (thread/node, fp32 Jacobi) + self-residual ----------------
__device__ __forceinline__ void jrotf(float& mpp, float& mqq, float& mpq,
                                      float& mrp, float& mrq,
                                      float& v0p, float& v0q,
                                      float& v1p, float& v1q,
                                      float& v2p, float& v2q) {
    float apq = mpq;
    if (fabsf(apq) < 1e-25f) { mpq = 0.f; return; }
    float theta = (mqq - mpp) / (2.f * apq);
    float t = copysignf(1.f, theta) / (fabsf(theta) + sqrtf(1.f + theta * theta));
    float c = rsqrtf(1.f + t * t);
    float s = t * c;
    mpp -= t * apq; mqq += t * apq; mpq = 0.f;
    float x = mrp, y = mrq;
    mrp = c * x - s * y; mrq = s * x + c * y;
    float a, b;
    a = v0p; b = v0q; v0p = c * a - s * b; v0q = s * a + c * b;
    a = v1p; b = v1q; v1p = c * a - s * b; v1q = s * a + c * b;
    a = v2p; b = v2q; v2p = c * a - s * b; v2q = s * a + c * b;
}

__global__ void svd_kernel(float* __restrict__ outR, float* __restrict__ outT) {
    int n = blockIdx.x * blockDim.x + threadIdx.x;
    if (n >= N_) return;
    const float* pm = g_pm + (size_t)n * 9;
    float a00 = pm[0], a01 = pm[1], a02 = pm[2];
    float a10 = pm[3], a11 = pm[4], a12 = pm[5];
    float a20 = pm[6], a21 = pm[7], a22 = pm[8];

    float m00 = a00 * a00 + a10 * a10 + a20 * a20;
    float m01 = a00 * a01 + a10 * a11 + a20 * a21;
    float m02 = a00 * a02 + a10 * a12 + a20 * a22;
    float m11 = a01 * a01 + a11 * a11 + a21 * a21;
    float m12 = a01 * a02 + a11 * a12 + a21 * a22;
    float m22 = a02 * a02 + a12 * a12 + a22 * a22;

    float v00 = 1, v01 = 0, v02 = 0;
    float v10 = 0, v11 = 1, v12 = 0;
    float v20 = 0, v21 = 0, v22 = 1;

#pragma unroll 1
    for (int sweep = 0; sweep < 7; sweep++) {
        jrotf(m00, m11, m01, m02, m12, v00, v01, v10, v11, v20, v21);
        jrotf(m00, m22, m02, m01, m12, v00, v02, v10, v12, v20, v22);
        jrotf(m11, m22, m12, m01, m02, v01, v02, v11, v12, v21, v22);
    }

    float e0 = m00, e1 = m11, e2 = m22;
    int i1 = 0; float eb = e0;
    if (e1 > eb) { i1 = 1; eb = e1; }
    if (e2 > eb) { i1 = 2; eb = e2; }
    int i3 = 0; float es = e0;
    if (e1 < es) { i3 = 1; es = e1; }
    if (e2 < es) { i3 = 2; es = e2; }
    if (i3 == i1) i3 = (i1 + 1) % 3;
    int i2 = 3 - i1 - i3;

    float v1x = (i1 == 0) ? v00 : ((i1 == 1) ? v01 : v02);
    float v1y = (i1 == 0) ? v10 : ((i1 == 1) ? v11 : v12);
    float v1z = (i1 == 0) ? v20 : ((i1 == 1) ? v21 : v22);
    float v2x = (i2 == 0) ? v00 : ((i2 == 1) ? v01 : v02);
    float v2y = (i2 == 0) ? v10 : ((i2 == 1) ? v11 : v12);
    float v2z = (i2 == 0) ? v20 : ((i2 == 1) ? v21 : v22);

    float u1x = a00 * v1x + a01 * v1y + a02 * v1z;
    float u1y = a10 * v1x + a11 * v1y + a12 * v1z;
    float u1z = a20 * v1x + a21 * v1y + a22 * v1z;
    float n1 = sqrtf(u1x * u1x + u1y * u1y + u1z * u1z) + 1e-30f;
    float in1 = 1.f / n1;
    u1x *= in1; u1y *= in1; u1z *= in1;

    float u2x = a00 * v2x + a01 * v2y + a02 * v2z;
    float u2y = a10 * v2x + a11 * v2y + a12 * v2z;
    float u2z = a20 * v2x + a21 * v2y + a22 * v2z;
    float d12 = u1x * u2x + u1y * u2y + u1z * u2z;
    u2x -= d12 * u1x; u2y -= d12 * u1y; u2z -= d12 * u1z;
    float n2 = sqrtf(u2x * u2x + u2y * u2y + u2z * u2z) + 1e-30f;
    float in2 = 1.f / n2;
    u2x *= in2; u2y *= in2; u2z *= in2;

    float u3x = u1y * u2z - u1z * u2y;
    float u3y = u1z * u2x - u1x * u2z;
    float u3z = u1x * u2y - u1y * u2x;
    float w3x = v1y * v2z - v1z * v2y;
    float w3y = v1z * v2x - v1x * v2z;
    float w3z = v1x * v2y - v1y * v2x;

    float R[3][3];
    float U1[3] = { u1x, u1y, u1z }, U2[3] = { u2x, u2y, u2z }, U3[3] = { u3x, u3y, u3z };
    float V1[3] = { v1x, v1y, v1z }, V2[3] = { v2x, v2y, v2z }, W3[3] = { w3x, w3y, w3z };
#pragma unroll
    for (int i = 0; i < 3; i++)
#pragma unroll
        for (int j = 0; j < 3; j++) {
            R[i][j] = U1[i] * V1[j] + U2[i] * V2[j] + U3[i] * W3[j];
            outR[(size_t)n * 9 + 3 * i + j] = R[i][j];
        }

    float sc0 = g_srcc[n * 3 + 0], sc1 = g_srcc[n * 3 + 1], sc2 = g_srcc[n * 3 + 2];
    float tc0 = g_tgtc[n * 3 + 0], tc1 = g_tgtc[n * 3 + 1], tc2 = g_tgtc[n * 3 + 2];
    float t0 = tc0 - (R[0][0] * sc0 + R[0][1] * sc1 + R[0][2] * sc2);
    float t1 = tc1 - (R[1][0] * sc0 + R[1][1] * sc1 + R[1][2] * sc2);
    float t2 = tc2 - (R[2][0] * sc0 + R[2][1] * sc1 + R[2][2] * sc2);
    outT[(size_t)n * 3 + 0] = t0;
    outT[(size_t)n * 3 + 1] = t1;
    outT[(size_t)n * 3 + 2] = t2;

    // self-residual g(n) = |R*pos(n) + t - pred(n)|^2 (edge residual depends only on col)
    const float* pp = g_pp + (size_t)n * 6;
    float sx = pp[0], sy = pp[1], sz = pp[2];
    float px = pp[3], py = pp[4], pz = pp[5];
    float rx = R[0][0] * sx + R[0][1] * sy + R[0][2] * sz + t0 - px;
    float ry = R[1][0] * sx + R[1][1] * sy + R[1][2] * sz + t1 - py;
    float rz = R[2][0] * sx + R[2][1] * sy + R[2][2] * sz + t2 - pz;
    g_res[n] = rx * rx + ry * ry + rz * rz;
}

// ---------------- per-node dst = mean of neighbor residuals (4B gather) ----------------
__global__ void dst_kernel(const int* __restrict__ col, float* __restrict__ dst) {
    int node = (blockIdx.x * blockDim.x + threadIdx.x) >> 5;
    int lane = threadIdx.x & 31;
    if (node >= N_) return;
    float d = g_res[col[node * DEG + lane]];
#pragma unroll
    for (int o = 16; o; o >>= 1) d += __shfl_xor_sync(0xffffffffu, d, o);
    if (lane == 0) dst[node] = d * (1.f / (float)DEG);
}

// ---------------- launch ----------------
extern "C" void kernel_launch(void* const* d_in, const int* in_sizes, int n_in,
                              void* d_out, int out_size) {
    const float* S   = (const float*)d_in[0];
    const float* Tf  = (const float*)d_in[1];
    const float* TP  = (const float*)d_in[2];
    const float* pos = (const float*)d_in[3];
    const int*   ei  = (const int*)d_in[4];
    const int*   col = ei + (size_t)N_ * DEG;

    float* out   = (float*)d_out;
    float* outR  = out;
    float* outTr = out + (size_t)N_ * 9;
    float* outD  = out + (size_t)N_ * 12;

    cudaFuncSetAttribute(mma_topk_kernel, cudaFuncAttributeMaxDynamicSharedMemorySize, MAIN_SMEM);

    convS_kernel<<<(NROWPAD * F_ + 255) / 256, 256>>>(S, pos);
    convT_tn_kernel<<<(CTILEPAD * 32 + 255) / 256, 256>>>(Tf);
    mma_topk_kernel<<<RTILES * QSPLIT, 512, MAIN_SMEM>>>();
    rescore_kernel<<<(N_ * 32 + 255) / 256, 256>>>(S, Tf, TP);
    accum_kernel<<<(N_ * DEG + 255) / 256, 256>>>(col);
    svd_kernel<<<(N_ + 127) / 128, 128>>>(outR, outTr);
    dst_kernel<<<(N_ * DEG + 255) / 256, 256>>>(col, outD);
}

// round 16
// speedup vs baseline: 1.1117x; 1.1117x over previous
#include <cuda_runtime.h>
#include <cuda_fp16.h>
#include <cstdint>

#define N_ 20000
#define T_ 6890
#define F_ 128
#define KTOP 6
#define KD 3                          /* per-thread packed-key list depth */
#define KCH 6                         /* per (row,chunk) output depth (exact top-6) */
#define DEG 32
#define QSPLIT 8
#define RTILES 157                    /* ceil(20000/128) */
#define NROWPAD (RTILES * 128)        /* 20096 */
#define CTILES 54                     /* ceil(6890/128) */
#define CTILEPAD (CTILES * 128)       /* 6912 */
#define VBIG 384.0f

// ---------------- device scratch ----------------
__device__ __align__(128) unsigned char g_Shi[NROWPAD * 256];   // fp16 [row][128]
__device__ __align__(128) unsigned char g_Thi[CTILEPAD * 256];  // fp16 [col][128]
__device__ __align__(128) float g_tnT[CTILEPAD];                // exact ||t||^2 (+inf pad)
__device__ __align__(128) float g_tnB[CTILEPAD];                // 384 - ||t||^2 (1e-20 pad)
__device__ uint32_t g_partK[N_ * QSPLIT * KCH];                 // packed keys
__device__ __align__(128) float g_pp[N_ * 6];                   // [pos3 | pred3] per node
__device__ float g_pm[N_ * 9];
__device__ float g_srcc[N_ * 3];
__device__ float g_tgtc[N_ * 3];
__device__ float g_res[N_];                                     // per-node residual magnitude^2

// ---------------- smem offsets (phase-1 kernel, triple-buffered B) ----------------
#define OFF_A    0                      /* 2 panels x 16KB = 32KB */
#define OFF_B(s) (32768 + (s) * 32768)  /* 3 stages x (2 panels x 16KB) */
#define OFF_TN   163840                 /* 7*128 floats = 3584B */
#define OFF_MRG  167424                 /* 128 rows x 24 keys = 12KB */
#define MAIN_SMEM 179712

// ---------------- helpers ----------------
__device__ __forceinline__ uint32_t smem_u32(const void* p) {
    uint32_t a;
    asm("{ .reg .u64 t; cvta.to.shared.u64 t, %1; cvt.u32.u64 %0, t; }" : "=r"(a) : "l"(p));
    return a;
}
__device__ __forceinline__ uint32_t sw(uint32_t x) { return x ^ ((x >> 3) & 0x70); }

__device__ __forceinline__ void cp_async16(uint32_t dst, const void* src) {
    asm volatile("cp.async.cg.shared.global [%0], [%1], 16;" :: "r"(dst), "l"(src));
}
__device__ __forceinline__ void cp_commit() { asm volatile("cp.async.commit_group;"); }
__device__ __forceinline__ void cp_wait1()  { asm volatile("cp.async.wait_group 1;"); }

__device__ __forceinline__ void ldsm4(uint32_t (&r)[4], uint32_t addr) {
    asm volatile("ldmatrix.sync.aligned.m8n8.x4.shared.b16 {%0,%1,%2,%3}, [%4];"
                 : "=r"(r[0]), "=r"(r[1]), "=r"(r[2]), "=r"(r[3]) : "r"(addr));
}
__device__ __forceinline__ void mma16816(float (&d)[4], const uint32_t (&a)[4], const uint32_t b0, const uint32_t b1) {
    asm volatile(
        "mma.sync.aligned.m16n8k16.row.col.f32.f16.f16.f32 "
        "{%0,%1,%2,%3}, {%4,%5,%6,%7}, {%8,%9}, {%0,%1,%2,%3};"
        : "+f"(d[0]), "+f"(d[1]), "+f"(d[2]), "+f"(d[3])
        : "r"(a[0]), "r"(a[1]), "r"(a[2]), "r"(a[3]), "r"(b0), "r"(b1));
}

// positive-float key: raw bits (order-isomorphic for v>0), low 13 bits = column index
__device__ __forceinline__ uint32_t pos_key(float v, int idx) {
    return (__float_as_uint(v) & 0xFFFFE000u) | (uint32_t)idx;
}

// branchless sorted-insert via IMNMX pairs
template <int K>
__device__ __forceinline__ void insKey(uint32_t k, uint32_t (&L)[K]) {
#pragma unroll
    for (int q = 0; q < K; q++) {
        uint32_t mx = max(L[q], k);
        k = min(L[q], k);
        L[q] = mx;
    }
}

template <int K>
__device__ __forceinline__ void insertK(float v, int idx, float (&tv)[K], int (&ti)[K]) {
    if (v <= tv[K - 1]) return;
    float cv = v; int ci = idx;
#pragma unroll
    for (int q = 0; q < K; q++) {
        if (cv > tv[q]) {
            float t1 = tv[q]; int t2 = ti[q];
            tv[q] = cv; ti[q] = ci;
            cv = t1; ci = t2;
        }
    }
}

// ---------------- convert kernels ----------------
__global__ void convS_kernel(const float* __restrict__ S, const float* __restrict__ pos) {
    int idx = blockIdx.x * blockDim.x + threadIdx.x;
    if (idx >= NROWPAD * F_) return;
    int n = idx >> 7, k = idx & 127;
    float x = (n < N_) ? S[(size_t)n * F_ + k] : 0.f;
    *reinterpret_cast<__half*>(g_Shi + (size_t)n * 256 + k * 2) = __float2half_rn(x);
    if (idx < N_ * 3) {
        int nn = idx / 3, j = idx - nn * 3;
        g_pp[nn * 6 + j] = pos[idx];
    }
}

// fused: fp16 convert of T + exact tn + shifted tnB (warp per target row)
__global__ void convT_tn_kernel(const float* __restrict__ Tf) {
    int c = (blockIdx.x * blockDim.x + threadIdx.x) >> 5;
    int lane = threadIdx.x & 31;
    if (c >= CTILEPAD) return;
    if (c >= T_) {
        reinterpret_cast<uint2*>(g_Thi + (size_t)c * 256)[lane] = make_uint2(0u, 0u);
        if (lane == 0) { g_tnT[c] = __int_as_float(0x7f800000); g_tnB[c] = 1e-20f; }
        return;
    }
    float4 v = reinterpret_cast<const float4*>(Tf + (size_t)c * F_)[lane];
    float s = v.x * v.x + v.y * v.y + v.z * v.z + v.w * v.w;
#pragma unroll
    for (int o = 16; o; o >>= 1) s += __shfl_xor_sync(0xffffffffu, s, o);
    __half2 h0 = __floats2half2_rn(v.x, v.y);
    __half2 h1 = __floats2half2_rn(v.z, v.w);
    uint2 pack;
    pack.x = *reinterpret_cast<uint32_t*>(&h0);
    pack.y = *reinterpret_cast<uint32_t*>(&h1);
    reinterpret_cast<uint2*>(g_Thi + (size_t)c * 256)[lane] = pack;
    if (lane == 0) { g_tnT[c] = s; g_tnB[c] = VBIG - s; }
}

// ---------------- phase 1: fp16 GEMM + packed-key approx selection ----------------
// warp grid 8(wm) x 2(wn): warp tile 16 rows x 64 cols; thread holds rows ra, ra+8
__device__ __forceinline__ void load_B(uint32_t sb, int stage, int ct, int tid) {
#pragma unroll
    for (int j = 0; j < 4; j++) {
        int id = tid + j * 512;
        int p = id >> 10, cid = id & 1023;
        int row = cid >> 3, cc = (cid & 7) * 16;
        cp_async16(sb + OFF_B(stage) + p * 16384 + sw(row * 128 + cc),
                   g_Thi + (size_t)(ct * 128 + row) * 256 + p * 128 + cc);
    }
}

__global__ __launch_bounds__(512, 1) void mma_topk_kernel() {
    extern __shared__ __align__(1024) unsigned char smem[];
    const uint32_t sb = smem_u32(smem);
    const float* tnS = reinterpret_cast<const float*>(smem + OFF_TN);
    uint32_t* mrg = reinterpret_cast<uint32_t*>(smem + OFF_MRG);

    const int tid  = threadIdx.x;
    const int lane = tid & 31;
    const int wid  = tid >> 5;
    const int wm   = wid >> 1;    // 0..7
    const int wn   = wid & 1;     // 0..1

    const int rblk = blockIdx.x >> 3;
    const int q    = blockIdx.x & 7;
    const int rb   = rblk * 128;
    const int t0   = (CTILES * q) / QSPLIT;
    const int t1   = (CTILES * (q + 1)) / QSPLIT;
    const int nt   = t1 - t0;

    uint32_t LA[KD], LB[KD];
#pragma unroll
    for (int k = 0; k < KD; k++) { LA[k] = 0u; LB[k] = 0u; }

    float acc[8][4];
#pragma unroll
    for (int ni = 0; ni < 8; ni++)
#pragma unroll
        for (int r = 0; r < 4; r++) acc[ni][r] = 0.f;

    // precomputed ldsm offsets
    uint32_t offA[4], offB4[4][4];
#pragma unroll
    for (int kk = 0; kk < 4; kk++)
        offA[kk] = sw((uint32_t)((wm * 16 + (lane & 15)) * 128 + kk * 32 + (lane >> 4) * 16));
#pragma unroll
    for (int nn = 0; nn < 4; nn++)
#pragma unroll
        for (int kk = 0; kk < 4; kk++)
            offB4[nn][kk] = sw((uint32_t)((wn * 64 + nn * 16 + ((lane >> 4) & 1) * 8 + (lane & 7)) * 128
                                          + kk * 32 + ((lane >> 3) & 1) * 16));

    // ---- prologue: group0 = {A, tnB, B0}; group1 = {B1} ----
#pragma unroll
    for (int j = 0; j < 4; j++) {
        int id = tid + j * 512;
        int p = id >> 10, cid = id & 1023;
        int row = cid >> 3, cc = (cid & 7) * 16;
        cp_async16(sb + OFF_A + p * 16384 + sw(row * 128 + cc),
                   g_Shi + (size_t)(rb + row) * 256 + p * 128 + cc);
    }
    if (tid < nt * 32)
        cp_async16(sb + OFF_TN + tid * 16, (const unsigned char*)(g_tnB + t0 * 128) + tid * 16);
    load_B(sb, 0, t0, tid);
    cp_commit();
    if (nt > 1) load_B(sb, 1, t0 + 1, tid);
    cp_commit();

    for (int i = 0; i < nt; i++) {
        int s = i % 3;
        cp_wait1();              // group(i) complete -> B(i) + (i==0: A,tn) ready
        __syncthreads();         // all threads done with stage being overwritten next
        if (i + 2 < nt) load_B(sb, (i + 2) % 3, t0 + i + 2, tid);
        cp_commit();

        // ---- compute: 2 k-half panels x 4 kk ----
#pragma unroll
        for (int p = 0; p < 2; p++) {
            uint32_t sa  = sb + OFF_A + p * 16384;
            uint32_t sbb = sb + OFF_B(s) + p * 16384;
#pragma unroll
            for (int kk = 0; kk < 4; kk++) {
                uint32_t b[8][2];
#pragma unroll
                for (int nn = 0; nn < 4; nn++) {
                    uint32_t bb[4];
                    ldsm4(bb, sbb + offB4[nn][kk]);
                    b[nn * 2][0] = bb[0]; b[nn * 2][1] = bb[1];
                    b[nn * 2 + 1][0] = bb[2]; b[nn * 2 + 1][1] = bb[3];
                }
                uint32_t a[4];
                ldsm4(a, sa + offA[kk]);
#pragma unroll
                for (int ni = 0; ni < 8; ni++) mma16816(acc[ni], a, b[ni][0], b[ni][1]);
            }
        }

        // ---- branchless packed-key epilogue (8 ops/value; v>0 by range analysis) ----
        {
            int cbg = (t0 + i) * 128;
            const float* tn = tnS + i * 128;
#pragma unroll
            for (int ni = 0; ni < 8; ni++) {
                int c0 = wn * 64 + ni * 8 + (lane & 3) * 2;
                float b0 = tn[c0], b1 = tn[c0 + 1];
                insKey<KD>(pos_key(fmaf(2.f, acc[ni][0], b0), cbg + c0),     LA);
                insKey<KD>(pos_key(fmaf(2.f, acc[ni][1], b1), cbg + c0 + 1), LA);
                insKey<KD>(pos_key(fmaf(2.f, acc[ni][2], b0), cbg + c0),     LB);
                insKey<KD>(pos_key(fmaf(2.f, acc[ni][3], b1), cbg + c0 + 1), LB);
                acc[ni][0] = acc[ni][1] = acc[ni][2] = acc[ni][3] = 0.f;
            }
        }
    }

    // ---- dump lists to smem; one thread per row builds exact chunk top-6 ----
    {
        int rowA = wm * 16 + (lane >> 2);
        int slot = wn * 12 + (lane & 3) * 3;
#pragma unroll
        for (int k = 0; k < KD; k++) {
            mrg[rowA * 24 + slot + k] = LA[k];
            mrg[(rowA + 8) * 24 + slot + k] = LB[k];
        }
    }
    __syncthreads();
    if (tid < 128) {
        uint32_t L6[KCH];
#pragma unroll
        for (int k = 0; k < KCH; k++) L6[k] = 0u;
#pragma unroll
        for (int i = 0; i < 24; i++) insKey<KCH>(mrg[tid * 24 + i], L6);
        int row = rb + tid;
        if (row < N_) {
            size_t base = ((size_t)row * QSPLIT + q) * KCH;
#pragma unroll
            for (int k = 0; k < KCH; k++) g_partK[base + k] = L6[k];
        }
    }
}

// ---------------- phase 2: merge 48 keys, exact fp32 rescore (serial, coalesced) ----------------
__global__ void rescore_kernel(const float* __restrict__ S, const float* __restrict__ Tf,
                               const float* __restrict__ TP) {
    int warp = (blockIdx.x * blockDim.x + threadIdx.x) >> 5;
    int lane = threadIdx.x & 31;
    if (warp >= N_) return;

    const uint32_t* K = g_partK + (size_t)warp * (QSPLIT * KCH);   // 48 keys
    uint32_t kA = K[lane];
    uint32_t kB = (lane < 16) ? K[32 + lane] : 0u;
    uint32_t hi = max(kA, kB), lo = min(kA, kB);

    uint32_t cand[8];
#pragma unroll
    for (int j = 0; j < 8; j++) {
        uint32_t m = __reduce_max_sync(0xffffffffu, hi);
        cand[j] = m;
        if (hi == m) { hi = lo; lo = 0u; }
    }

    // exact fp32 rescore of the 8 candidates (full-warp coalesced row reads)
    float4 s4 = reinterpret_cast<const float4*>(S + (size_t)warp * F_)[lane];
    float bv[KTOP]; int bi[KTOP];
#pragma unroll
    for (int k = 0; k < KTOP; k++) { bv[k] = __int_as_float(0xff800000); bi[k] = 0; }
#pragma unroll
    for (int j = 0; j < 8; j++) {
        int idx = (int)(cand[j] & 8191u);
        idx = (idx < T_) ? idx : (T_ - 1);
        float4 t4 = reinterpret_cast<const float4*>(Tf + (size_t)idx * F_)[lane];
        float d = s4.x * t4.x + s4.y * t4.y + s4.z * t4.z + s4.w * t4.w;
#pragma unroll
        for (int o = 16; o; o >>= 1) d += __shfl_xor_sync(0xffffffffu, d, o);
        float sc = 2.f * d - g_tnT[idx];
        insertK<KTOP>(sc, idx, bv, bi);
    }

    if (lane == 0) {
        float m = bv[0];
        float w[KTOP], sum = 0.f;
#pragma unroll
        for (int k = 0; k < KTOP; k++) { w[k] = expf(bv[k] - m); sum += w[k]; }
        float inv = 1.f / sum;
        float px = 0.f, py = 0.f, pz = 0.f;
#pragma unroll
        for (int k = 0; k < KTOP; k++) {
            float wk = w[k] * inv;
            const float* tp = TP + (size_t)bi[k] * 3;
            px = fmaf(wk, tp[0], px);
            py = fmaf(wk, tp[1], py);
            pz = fmaf(wk, tp[2], pz);
        }
        g_pp[warp * 6 + 3] = px;
        g_pp[warp * 6 + 4] = py;
        g_pp[warp * 6 + 5] = pz;
    }
}

// ---------------- per-node centers + covariance (warp/node, packed pp gather) ----------------
__global__ void accum_kernel(const int* __restrict__ col) {
    int node = (blockIdx.x * blockDim.x + threadIdx.x) >> 5;
    int lane = threadIdx.x & 31;
    if (node >= N_) return;
    int c = col[node * DEG + lane];
    const float2* pp = reinterpret_cast<const float2*>(g_pp + (size_t)c * 6);
    float2 p0 = pp[0], p1 = pp[1], p2 = pp[2];
    float sx = p0.x, sy = p0.y, sz = p1.x;
    float tx = p1.y, ty = p2.x, tz = p2.y;
    float v[15] = { sx, sy, sz, tx, ty, tz,
                    sx * tx, sx * ty, sx * tz,
                    sy * tx, sy * ty, sy * tz,
                    sz * tx, sz * ty, sz * tz };
#pragma unroll
    for (int k = 0; k < 15; k++)
#pragma unroll
        for (int o = 16; o; o >>= 1) v[k] += __shfl_xor_sync(0xffffffffu, v[k], o);
    if (lane == 0) {
        const float invd = 1.f / (float)DEG;
        float scx = v[0] * invd, scy = v[1] * invd, scz = v[2] * invd;
        float tcx = v[3] * invd, tcy = v[4] * invd, tcz = v[5] * invd;
        g_srcc[node * 3 + 0] = scx; g_srcc[node * 3 + 1] = scy; g_srcc[node * 3 + 2] = scz;
        g_tgtc[node * 3 + 0] = tcx; g_tgtc[node * 3 + 1] = tcy; g_tgtc[node * 3 + 2] = tcz;
        float sc[3] = { scx, scy, scz };
        float tc[3] = { tcx, tcy, tcz };
#pragma unroll
        for (int i = 0; i < 3; i++)
#pragma unroll
            for (int j = 0; j < 3; j++)
                g_pm[node * 9 + 3 * i + j] = v[6 + 3 * i + j] - (float)DEG * sc[i] * tc[j];
    }
}

// ---------------- 3x3 Procrustes SVD (thread/node, fp32 Jacobi) + self-residual ----------------
__device__ __forceinline__ void jrotf(float& mpp, float& mqq, float& mpq,
                                      float& mrp, float& mrq,
                                      float& v0p, float& v0q,
                                      float& v1p, float& v1q,
                                      float& v2p, float& v2q) {
    float apq = mpq;
    if (fabsf(apq) < 1e-25f) { mpq = 0.f; return; }
    float theta = (mqq - mpp) / (2.f * apq);
    float t = copysignf(1.f, theta) / (fabsf(theta) + sqrtf(1.f + theta * theta));
    float c = rsqrtf(1.f + t * t);
    float s = t * c;
    mpp -= t * apq; mqq += t * apq; mpq = 0.f;
    float x = mrp, y = mrq;
    mrp = c * x - s * y; mrq = s * x + c * y;
    float a, b;
    a = v0p; b = v0q; v0p = c * a - s * b; v0q = s * a + c * b;
    a = v1p; b = v1q; v1p = c * a - s * b; v1q = s * a + c * b;
    a = v2p; b = v2q; v2p = c * a - s * b; v2q = s * a + c * b;
}

__global__ void svd_kernel(float* __restrict__ outR, float* __restrict__ outT) {
    int n = blockIdx.x * blockDim.x + threadIdx.x;
    if (n >= N_) return;
    const float* pm = g_pm + (size_t)n * 9;
    float a00 = pm[0], a01 = pm[1], a02 = pm[2];
    float a10 = pm[3], a11 = pm[4], a12 = pm[5];
    float a20 = pm[6], a21 = pm[7], a22 = pm[8];

    float m00 = a00 * a00 + a10 * a10 + a20 * a20;
    float m01 = a00 * a01 + a10 * a11 + a20 * a21;
    float m02 = a00 * a02 + a10 * a12 + a20 * a22;
    float m11 = a01 * a01 + a11 * a11 + a21 * a21;
    float m12 = a01 * a02 + a11 * a12 + a21 * a22;
    float m22 = a02 * a02 + a12 * a12 + a22 * a22;

    float v00 = 1, v01 = 0, v02 = 0;
    float v10 = 0, v11 = 1, v12 = 0;
    float v20 = 0, v21 = 0, v22 = 1;

#pragma unroll 1
    for (int sweep = 0; sweep < 7; sweep++) {
        jrotf(m00, m11, m01, m02, m12, v00, v01, v10, v11, v20, v21);
        jrotf(m00, m22, m02, m01, m12, v00, v02, v10, v12, v20, v22);
        jrotf(m11, m22, m12, m01, m02, v01, v02, v11, v12, v21, v22);
    }

    float e0 = m00, e1 = m11, e2 = m22;
    int i1 = 0; float eb = e0;
    if (e1 > eb) { i1 = 1; eb = e1; }
    if (e2 > eb) { i1 = 2; eb = e2; }
    int i3 = 0; float es = e0;
    if (e1 < es) { i3 = 1; es = e1; }
    if (e2 < es) { i3 = 2; es = e2; }
    if (i3 == i1) i3 = (i1 + 1) % 3;
    int i2 = 3 - i1 - i3;

    float v1x = (i1 == 0) ? v00 : ((i1 == 1) ? v01 : v02);
    float v1y = (i1 == 0) ? v10 : ((i1 == 1) ? v11 : v12);
    float v1z = (i1 == 0) ? v20 : ((i1 == 1) ? v21 : v22);
    float v2x = (i2 == 0) ? v00 : ((i2 == 1) ? v01 : v02);
    float v2y = (i2 == 0) ? v10 : ((i2 == 1) ? v11 : v12);
    float v2z = (i2 == 0) ? v20 : ((i2 == 1) ? v21 : v22);

    float u1x = a00 * v1x + a01 * v1y + a02 * v1z;
    float u1y = a10 * v1x + a11 * v1y + a12 * v1z;
    float u1z = a20 * v1x + a21 * v1y + a22 * v1z;
    float n1 = sqrtf(u1x * u1x + u1y * u1y + u1z * u1z) + 1e-30f;
    float in1 = 1.f / n1;
    u1x *= in1; u1y *= in1; u1z *= in1;

    float u2x = a00 * v2x + a01 * v2y + a02 * v2z;
    float u2y = a10 * v2x + a11 * v2y + a12 * v2z;
    float u2z = a20 * v2x + a21 * v2y + a22 * v2z;
    float d12 = u1x * u2x + u1y * u2y + u1z * u2z;
    u2x -= d12 * u1x; u2y -= d12 * u1y; u2z -= d12 * u1z;
    float n2 = sqrtf(u2x * u2x + u2y * u2y + u2z * u2z) + 1e-30f;
    float in2 = 1.f / n2;
    u2x *= in2; u2y *= in2; u2z *= in2;

    float u3x = u1y * u2z - u1z * u2y;
    float u3y = u1z * u2x - u1x * u2z;
    float u3z = u1x * u2y - u1y * u2x;
    float w3x = v1y * v2z - v1z * v2y;
    float w3y = v1z * v2x - v1x * v2z;
    float w3z = v1x * v2y - v1y * v2x;

    float R[3][3];
    float U1[3] = { u1x, u1y, u1z }, U2[3] = { u2x, u2y, u2z }, U3[3] = { u3x, u3y, u3z };
    float V1[3] = { v1x, v1y, v1z }, V2[3] = { v2x, v2y, v2z }, W3[3] = { w3x, w3y, w3z };
#pragma unroll
    for (int i = 0; i < 3; i++)
#pragma unroll
        for (int j = 0; j < 3; j++) {
            R[i][j] = U1[i] * V1[j] + U2[i] * V2[j] + U3[i] * W3[j];
            outR[(size_t)n * 9 + 3 * i + j] = R[i][j];
        }

    float sc0 = g_srcc[n * 3 + 0], sc1 = g_srcc[n * 3 + 1], sc2 = g_srcc[n * 3 + 2];
    float tc0 = g_tgtc[n * 3 + 0], tc1 = g_tgtc[n * 3 + 1], tc2 = g_tgtc[n * 3 + 2];
    float t0 = tc0 - (R[0][0] * sc0 + R[0][1] * sc1 + R[0][2] * sc2);
    float t1 = tc1 - (R[1][0] * sc0 + R[1][1] * sc1 + R[1][2] * sc2);
    float t2 = tc2 - (R[2][0] * sc0 + R[2][1] * sc1 + R[2][2] * sc2);
    outT[(size_t)n * 3 + 0] = t0;
    outT[(size_t)n * 3 + 1] = t1;
    outT[(size_t)n * 3 + 2] = t2;

    // self-residual g(n) = |R*pos(n) + t - pred(n)|^2 (edge residual depends only on col)
    const float* pp = g_pp + (size_t)n * 6;
    float sx = pp[0], sy = pp[1], sz = pp[2];
    float px = pp[3], py = pp[4], pz = pp[5];
    float rx = R[0][0] * sx + R[0][1] * sy + R[0][2] * sz + t0 - px;
    float ry = R[1][0] * sx + R[1][1] * sy + R[1][2] * sz + t1 - py;
    float rz = R[2][0] * sx + R[2][1] * sy + R[2][2] * sz + t2 - pz;
    g_res[n] = rx * rx + ry * ry + rz * rz;
}

// ---------------- per-node dst = mean of neighbor residuals (4B gather) ----------------
__global__ void dst_kernel(const int* __restrict__ col, float* __restrict__ dst) {
    int node = (blockIdx.x * blockDim.x + threadIdx.x) >> 5;
    int lane = threadIdx.x & 31;
    if (node >= N_) return;
    float d = g_res[col[node * DEG + lane]];
#pragma unroll
    for (int o = 16; o; o >>= 1) d += __shfl_xor_sync(0xffffffffu, d, o);
    if (lane == 0) dst[node] = d * (1.f / (float)DEG);
}

// ---------------- launch ----------------
extern "C" void kernel_launch(void* const* d_in, const int* in_sizes, int n_in,
                              void* d_out, int out_size) {
    const float* S   = (const float*)d_in[0];
    const float* Tf  = (const float*)d_in[1];
    const float* TP  = (const float*)d_in[2];
    const float* pos = (const float*)d_in[3];
    const int*   ei  = (const int*)d_in[4];
    const int*   col = ei + (size_t)N_ * DEG;

    float* out   = (float*)d_out;
    float* outR  = out;
    float* outTr = out + (size_t)N_ * 9;
    float* outD  = out + (size_t)N_ * 12;

    cudaFuncSetAttribute(mma_topk_kernel, cudaFuncAttributeMaxDynamicSharedMemorySize, MAIN_SMEM);

    convS_kernel<<<(NROWPAD * F_ + 255) / 256, 256>>>(S, pos);
    convT_tn_kernel<<<(CTILEPAD * 32 + 255) / 256, 256>>>(Tf);
    mma_topk_kernel<<<RTILES * QSPLIT, 512, MAIN_SMEM>>>();
    rescore_kernel<<<(N_ * 32 + 255) / 256, 256>>>(S, Tf, TP);
    accum_kernel<<<(N_ * DEG + 255) / 256, 256>>>(col);
    svd_kernel<<<(N_ + 127) / 128, 128>>>(outR, outTr);
    dst_kernel<<<(N_ * DEG + 255) / 256, 256>>>(col, outD);
}

// round 17
// speedup vs baseline: 1.1197x; 1.0072x over previous
#include <cuda_runtime.h>
#include <cuda_fp16.h>
#include <cstdint>

#define N_ 20000
#define T_ 6890
#define F_ 128
#define KTOP 6
#define KD 3                          /* per-thread packed-key list depth */
#define KCH 6                         /* per (row,chunk) output depth (exact top-6) */
#define DEG 32
#define QSPLIT 8
#define RTILES 157                    /* ceil(20000/128) */
#define NROWPAD (RTILES * 128)        /* 20096 */
#define CTILES 54                     /* ceil(6890/128) */
#define CTILEPAD (CTILES * 128)       /* 6912 */
#define VBIG 384.0f

// ---------------- device scratch ----------------
__device__ __align__(128) unsigned char g_Shi[NROWPAD * 256];   // fp16 [row][128]
__device__ __align__(128) unsigned char g_Thi[CTILEPAD * 256];  // fp16 [col][128]
__device__ __align__(128) float g_tnT[CTILEPAD];                // exact ||t||^2 (+inf pad)
__device__ __align__(128) float g_tnB[CTILEPAD];                // 384 - ||t||^2 (1e-20 pad)
__device__ uint32_t g_partK[N_ * QSPLIT * KCH];                 // packed keys
__device__ __align__(128) float g_pp[N_ * 6];                   // [pos3 | pred3] per node
__device__ float g_pm[N_ * 9];
__device__ float g_srcc[N_ * 3];
__device__ float g_tgtc[N_ * 3];
__device__ float g_res[N_];                                     // per-node residual magnitude^2

// ---------------- smem offsets (phase-1 kernel, quad-buffered B) ----------------
#define OFF_A    0                      /* 2 panels x 16KB = 32KB */
#define OFF_B(s) (32768 + (s) * 32768)  /* 4 stages x (2 panels x 16KB) -> ends at 160KB */
#define OFF_TN   163840                 /* 7*128 floats = 3584B */
#define OFF_MRG  167424                 /* 128 rows x 24 keys = 12KB */
#define MAIN_SMEM 179712

// ---------------- helpers ----------------
__device__ __forceinline__ uint32_t smem_u32(const void* p) {
    uint32_t a;
    asm("{ .reg .u64 t; cvta.to.shared.u64 t, %1; cvt.u32.u64 %0, t; }" : "=r"(a) : "l"(p));
    return a;
}
__device__ __forceinline__ uint32_t sw(uint32_t x) { return x ^ ((x >> 3) & 0x70); }

__device__ __forceinline__ void cp_async16(uint32_t dst, const void* src) {
    asm volatile("cp.async.cg.shared.global [%0], [%1], 16;" :: "r"(dst), "l"(src));
}
__device__ __forceinline__ void cp_commit() { asm volatile("cp.async.commit_group;"); }
__device__ __forceinline__ void cp_wait2()  { asm volatile("cp.async.wait_group 2;"); }

__device__ __forceinline__ void ldsm4(uint32_t (&r)[4], uint32_t addr) {
    asm volatile("ldmatrix.sync.aligned.m8n8.x4.shared.b16 {%0,%1,%2,%3}, [%4];"
                 : "=r"(r[0]), "=r"(r[1]), "=r"(r[2]), "=r"(r[3]) : "r"(addr));
}
__device__ __forceinline__ void mma16816(float (&d)[4], const uint32_t (&a)[4], const uint32_t b0, const uint32_t b1) {
    asm volatile(
        "mma.sync.aligned.m16n8k16.row.col.f32.f16.f16.f32 "
        "{%0,%1,%2,%3}, {%4,%5,%6,%7}, {%8,%9}, {%0,%1,%2,%3};"
        : "+f"(d[0]), "+f"(d[1]), "+f"(d[2]), "+f"(d[3])
        : "r"(a[0]), "r"(a[1]), "r"(a[2]), "r"(a[3]), "r"(b0), "r"(b1));
}
// zero-accumulator variant: d = A*B + 0 (kills per-tile acc resets)
__device__ __forceinline__ void mma16816_z(float (&d)[4], const uint32_t (&a)[4], const uint32_t b0, const uint32_t b1) {
    asm volatile(
        "mma.sync.aligned.m16n8k16.row.col.f32.f16.f16.f32 "
        "{%0,%1,%2,%3}, {%4,%5,%6,%7}, {%8,%9}, {%10,%11,%12,%13};"
        : "=f"(d[0]), "=f"(d[1]), "=f"(d[2]), "=f"(d[3])
        : "r"(a[0]), "r"(a[1]), "r"(a[2]), "r"(a[3]), "r"(b0), "r"(b1),
          "f"(0.f), "f"(0.f), "f"(0.f), "f"(0.f));
}

// positive-float key: raw bits (order-isomorphic for v>0), low 13 bits = column index
__device__ __forceinline__ uint32_t pos_key(float v, int idx) {
    return (__float_as_uint(v) & 0xFFFFE000u) | (uint32_t)idx;
}

// branchless sorted-insert via IMNMX pairs
template <int K>
__device__ __forceinline__ void insKey(uint32_t k, uint32_t (&L)[K]) {
#pragma unroll
    for (int q = 0; q < K; q++) {
        uint32_t mx = max(L[q], k);
        k = min(L[q], k);
        L[q] = mx;
    }
}

template <int K>
__device__ __forceinline__ void insertK(float v, int idx, float (&tv)[K], int (&ti)[K]) {
    if (v <= tv[K - 1]) return;
    float cv = v; int ci = idx;
#pragma unroll
    for (int q = 0; q < K; q++) {
        if (cv > tv[q]) {
            float t1 = tv[q]; int t2 = ti[q];
            tv[q] = cv; ti[q] = ci;
            cv = t1; ci = t2;
        }
    }
}

// ---------------- convert kernels ----------------
__global__ void convS_kernel(const float* __restrict__ S, const float* __restrict__ pos) {
    int idx = blockIdx.x * blockDim.x + threadIdx.x;
    if (idx >= NROWPAD * F_) return;
    int n = idx >> 7, k = idx & 127;
    float x = (n < N_) ? S[(size_t)n * F_ + k] : 0.f;
    *reinterpret_cast<__half*>(g_Shi + (size_t)n * 256 + k * 2) = __float2half_rn(x);
    if (idx < N_ * 3) {
        int nn = idx / 3, j = idx - nn * 3;
        g_pp[nn * 6 + j] = pos[idx];
    }
}

// fused: fp16 convert of T + exact tn + shifted tnB (warp per target row)
__global__ void convT_tn_kernel(const float* __restrict__ Tf) {
    int c = (blockIdx.x * blockDim.x + threadIdx.x) >> 5;
    int lane = threadIdx.x & 31;
    if (c >= CTILEPAD) return;
    if (c >= T_) {
        reinterpret_cast<uint2*>(g_Thi + (size_t)c * 256)[lane] = make_uint2(0u, 0u);
        if (lane == 0) { g_tnT[c] = __int_as_float(0x7f800000); g_tnB[c] = 1e-20f; }
        return;
    }
    float4 v = reinterpret_cast<const float4*>(Tf + (size_t)c * F_)[lane];
    float s = v.x * v.x + v.y * v.y + v.z * v.z + v.w * v.w;
#pragma unroll
    for (int o = 16; o; o >>= 1) s += __shfl_xor_sync(0xffffffffu, s, o);
    __half2 h0 = __floats2half2_rn(v.x, v.y);
    __half2 h1 = __floats2half2_rn(v.z, v.w);
    uint2 pack;
    pack.x = *reinterpret_cast<uint32_t*>(&h0);
    pack.y = *reinterpret_cast<uint32_t*>(&h1);
    reinterpret_cast<uint2*>(g_Thi + (size_t)c * 256)[lane] = pack;
    if (lane == 0) { g_tnT[c] = s; g_tnB[c] = VBIG - s; }
}

// ---------------- phase 1: fp16 GEMM + packed-key approx selection ----------------
// warp grid 8(wm) x 2(wn): warp tile 16 rows x 64 cols; thread holds rows ra, ra+8
__device__ __forceinline__ void load_B(uint32_t sb, int stage, int ct, int tid) {
#pragma unroll
    for (int j = 0; j < 4; j++) {
        int id = tid + j * 512;
        int p = id >> 10, cid = id & 1023;
        int row = cid >> 3, cc = (cid & 7) * 16;
        cp_async16(sb + OFF_B(stage) + p * 16384 + sw(row * 128 + cc),
                   g_Thi + (size_t)(ct * 128 + row) * 256 + p * 128 + cc);
    }
}

__global__ __launch_bounds__(512, 1) void mma_topk_kernel() {
    extern __shared__ __align__(1024) unsigned char smem[];
    const uint32_t sb = smem_u32(smem);
    const float* tnS = reinterpret_cast<const float*>(smem + OFF_TN);
    uint32_t* mrg = reinterpret_cast<uint32_t*>(smem + OFF_MRG);

    const int tid  = threadIdx.x;
    const int lane = tid & 31;
    const int wid  = tid >> 5;
    const int wm   = wid >> 1;    // 0..7
    const int wn   = wid & 1;     // 0..1

    const int rblk = blockIdx.x >> 3;
    const int q    = blockIdx.x & 7;
    const int rb   = rblk * 128;
    const int t0   = (CTILES * q) / QSPLIT;
    const int t1   = (CTILES * (q + 1)) / QSPLIT;
    const int nt   = t1 - t0;

    uint32_t LA[KD], LB[KD];
#pragma unroll
    for (int k = 0; k < KD; k++) { LA[k] = 0u; LB[k] = 0u; }

    float acc[8][4];

    // precomputed ldsm offsets
    uint32_t offA[4], offB4[4][4];
#pragma unroll
    for (int kk = 0; kk < 4; kk++)
        offA[kk] = sw((uint32_t)((wm * 16 + (lane & 15)) * 128 + kk * 32 + (lane >> 4) * 16));
#pragma unroll
    for (int nn = 0; nn < 4; nn++)
#pragma unroll
        for (int kk = 0; kk < 4; kk++)
            offB4[nn][kk] = sw((uint32_t)((wn * 64 + nn * 16 + ((lane >> 4) & 1) * 8 + (lane & 7)) * 128
                                          + kk * 32 + ((lane >> 3) & 1) * 16));

    // ---- prologue: group0 = {A, tnB, B0}; group1 = {B1}; group2 = {B2} ----
#pragma unroll
    for (int j = 0; j < 4; j++) {
        int id = tid + j * 512;
        int p = id >> 10, cid = id & 1023;
        int row = cid >> 3, cc = (cid & 7) * 16;
        cp_async16(sb + OFF_A + p * 16384 + sw(row * 128 + cc),
                   g_Shi + (size_t)(rb + row) * 256 + p * 128 + cc);
    }
    if (tid < nt * 32)
        cp_async16(sb + OFF_TN + tid * 16, (const unsigned char*)(g_tnB + t0 * 128) + tid * 16);
    load_B(sb, 0, t0, tid);
    cp_commit();
    if (nt > 1) load_B(sb, 1, t0 + 1, tid);
    cp_commit();
    if (nt > 2) load_B(sb, 2, t0 + 2, tid);
    cp_commit();

    for (int i = 0; i < nt; i++) {
        int s = i & 3;
        cp_wait2();              // group(i) complete -> B(i) + (i==0: A,tn) ready
        __syncthreads();         // all threads done with the stage being overwritten next
        if (i + 3 < nt) load_B(sb, (i + 3) & 3, t0 + i + 3, tid);
        cp_commit();

        // ---- compute: 2 k-half panels x 4 kk (first step uses zero-C MMA) ----
#pragma unroll
        for (int p = 0; p < 2; p++) {
            uint32_t sa  = sb + OFF_A + p * 16384;
            uint32_t sbb = sb + OFF_B(s) + p * 16384;
#pragma unroll
            for (int kk = 0; kk < 4; kk++) {
                uint32_t b[8][2];
#pragma unroll
                for (int nn = 0; nn < 4; nn++) {
                    uint32_t bb[4];
                    ldsm4(bb, sbb + offB4[nn][kk]);
                    b[nn * 2][0] = bb[0]; b[nn * 2][1] = bb[1];
                    b[nn * 2 + 1][0] = bb[2]; b[nn * 2 + 1][1] = bb[3];
                }
                uint32_t a[4];
                ldsm4(a, sa + offA[kk]);
                if (p == 0 && kk == 0) {
#pragma unroll
                    for (int ni = 0; ni < 8; ni++) mma16816_z(acc[ni], a, b[ni][0], b[ni][1]);
                } else {
#pragma unroll
                    for (int ni = 0; ni < 8; ni++) mma16816(acc[ni], a, b[ni][0], b[ni][1]);
                }
            }
        }

        // ---- branchless packed-key epilogue (no acc reset needed) ----
        {
            int cbg = (t0 + i) * 128;
            const float* tn = tnS + i * 128;
#pragma unroll
            for (int ni = 0; ni < 8; ni++) {
                int c0 = wn * 64 + ni * 8 + (lane & 3) * 2;
                float b0 = tn[c0], b1 = tn[c0 + 1];
                insKey<KD>(pos_key(fmaf(2.f, acc[ni][0], b0), cbg + c0),     LA);
                insKey<KD>(pos_key(fmaf(2.f, acc[ni][1], b1), cbg + c0 + 1), LA);
                insKey<KD>(pos_key(fmaf(2.f, acc[ni][2], b0), cbg + c0),     LB);
                insKey<KD>(pos_key(fmaf(2.f, acc[ni][3], b1), cbg + c0 + 1), LB);
            }
        }
    }

    // ---- dump lists to smem; one thread per row builds exact chunk top-6 ----
    {
        int rowA = wm * 16 + (lane >> 2);
        int slot = wn * 12 + (lane & 3) * 3;
#pragma unroll
        for (int k = 0; k < KD; k++) {
            mrg[rowA * 24 + slot + k] = LA[k];
            mrg[(rowA + 8) * 24 + slot + k] = LB[k];
        }
    }
    __syncthreads();
    if (tid < 128) {
        uint32_t L6[KCH];
#pragma unroll
        for (int k = 0; k < KCH; k++) L6[k] = 0u;
#pragma unroll
        for (int i = 0; i < 24; i++) insKey<KCH>(mrg[tid * 24 + i], L6);
        int row = rb + tid;
        if (row < N_) {
            size_t base = ((size_t)row * QSPLIT + q) * KCH;
#pragma unroll
            for (int k = 0; k < KCH; k++) g_partK[base + k] = L6[k];
        }
    }
}

// ---------------- phase 2: merge 48 keys, exact fp32 rescore (serial, coalesced) ----------------
__global__ void rescore_kernel(const float* __restrict__ S, const float* __restrict__ Tf,
                               const float* __restrict__ TP) {
    int warp = (blockIdx.x * blockDim.x + threadIdx.x) >> 5;
    int lane = threadIdx.x & 31;
    if (warp >= N_) return;

    const uint32_t* K = g_partK + (size_t)warp * (QSPLIT * KCH);   // 48 keys
    uint32_t kA = K[lane];
    uint32_t kB = (lane < 16) ? K[32 + lane] : 0u;
    uint32_t hi = max(kA, kB), lo = min(kA, kB);

    uint32_t cand[8];
#pragma unroll
    for (int j = 0; j < 8; j++) {
        uint32_t m = __reduce_max_sync(0xffffffffu, hi);
        cand[j] = m;
        if (hi == m) { hi = lo; lo = 0u; }
    }

    // exact fp32 rescore of the 8 candidates (full-warp coalesced row reads)
    float4 s4 = reinterpret_cast<const float4*>(S + (size_t)warp * F_)[lane];
    float bv[KTOP]; int bi[KTOP];
#pragma unroll
    for (int k = 0; k < KTOP; k++) { bv[k] = __int_as_float(0xff800000); bi[k] = 0; }
#pragma unroll
    for (int j = 0; j < 8; j++) {
        int idx = (int)(cand[j] & 8191u);
        idx = (idx < T_) ? idx : (T_ - 1);
        float4 t4 = reinterpret_cast<const float4*>(Tf + (size_t)idx * F_)[lane];
        float d = s4.x * t4.x + s4.y * t4.y + s4.z * t4.z + s4.w * t4.w;
#pragma unroll
        for (int o = 16; o; o >>= 1) d += __shfl_xor_sync(0xffffffffu, d, o);
        float sc = 2.f * d - g_tnT[idx];
        insertK<KTOP>(sc, idx, bv, bi);
    }

    if (lane == 0) {
        float m = bv[0];
        float w[KTOP], sum = 0.f;
#pragma unroll
        for (int k = 0; k < KTOP; k++) { w[k] = expf(bv[k] - m); sum += w[k]; }
        float inv = 1.f / sum;
        float px = 0.f, py = 0.f, pz = 0.f;
#pragma unroll
        for (int k = 0; k < KTOP; k++) {
            float wk = w[k] * inv;
            const float* tp = TP + (size_t)bi[k] * 3;
            px = fmaf(wk, tp[0], px);
            py = fmaf(wk, tp[1], py);
            pz = fmaf(wk, tp[2], pz);
        }
        g_pp[warp * 6 + 3] = px;
        g_pp[warp * 6 + 4] = py;
        g_pp[warp * 6 + 5] = pz;
    }
}

// ---------------- per-node centers + covariance (warp/node, packed pp gather) ----------------
__global__ void accum_kernel(const int* __restrict__ col) {
    int node = (blockIdx.x * blockDim.x + threadIdx.x) >> 5;
    int lane = threadIdx.x & 31;
    if (node >= N_) return;
    int c = col[node * DEG + lane];
    const float2* pp = reinterpret_cast<const float2*>(g_pp + (size_t)c * 6);
    float2 p0 = pp[0], p1 = pp[1], p2 = pp[2];
    float sx = p0.x, sy = p0.y, sz = p1.x;
    float tx = p1.y, ty = p2.x, tz = p2.y;
    float v[15] = { sx, sy, sz, tx, ty, tz,
                    sx * tx, sx * ty, sx * tz,
                    sy * tx, sy * ty, sy * tz,
                    sz * tx, sz * ty, sz * tz };
#pragma unroll
    for (int k = 0; k < 15; k++)
#pragma unroll
        for (int o = 16; o; o >>= 1) v[k] += __shfl_xor_sync(0xffffffffu, v[k], o);
    if (lane == 0) {
        const float invd = 1.f / (float)DEG;
        float scx = v[0] * invd, scy = v[1] * invd, scz = v[2] * invd;
        float tcx = v[3] * invd, tcy = v[4] * invd, tcz = v[5] * invd;
        g_srcc[node * 3 + 0] = scx; g_srcc[node * 3 + 1] = scy; g_srcc[node * 3 + 2] = scz;
        g_tgtc[node * 3 + 0] = tcx; g_tgtc[node * 3 + 1] = tcy; g_tgtc[node * 3 + 2] = tcz;
        float sc[3] = { scx, scy, scz };
        float tc[3] = { tcx, tcy, tcz };
#pragma unroll
        for (int i = 0; i < 3; i++)
#pragma unroll
            for (int j = 0; j < 3; j++)
                g_pm[node * 9 + 3 * i + j] = v[6 + 3 * i + j] - (float)DEG * sc[i] * tc[j];
    }
}

// ---------------- 3x3 Procrustes SVD (thread/node, fp32 Jacobi) + self-residual ----------------
__device__ __forceinline__ void jrotf(float& mpp, float& mqq, float& mpq,
                                      float& mrp, float& mrq,
                                      float& v0p, float& v0q,
                                      float& v1p, float& v1q,
                                      float& v2p, float& v2q) {
    float apq = mpq;
    if (fabsf(apq) < 1e-25f) { mpq = 0.f; return; }
    float theta = (mqq - mpp) / (2.f * apq);
    float t = copysignf(1.f, theta) / (fabsf(theta) + sqrtf(1.f + theta * theta));
    float c = rsqrtf(1.f + t * t);
    float s = t * c;
    mpp -= t * apq; mqq += t * apq; mpq = 0.f;
    float x = mrp, y = mrq;
    mrp = c * x - s * y; mrq = s * x + c * y;
    float a, b;
    a = v0p; b = v0q; v0p = c * a - s * b; v0q = s * a + c * b;
    a = v1p; b = v1q; v1p = c * a - s * b; v1q = s * a + c * b;
    a = v2p; b = v2q; v2p = c * a - s * b; v2q = s * a + c * b;
}

__global__ void svd_kernel(float* __restrict__ outR, float* __restrict__ outT) {
    int n = blockIdx.x * blockDim.x + threadIdx.x;
    if (n >= N_) return;
    const float* pm = g_pm + (size_t)n * 9;
    float a00 = pm[0], a01 = pm[1], a02 = pm[2];
    float a10 = pm[3], a11 = pm[4], a12 = pm[5];
    float a20 = pm[6], a21 = pm[7], a22 = pm[8];

    float m00 = a00 * a00 + a10 * a10 + a20 * a20;
    float m01 = a00 * a01 + a10 * a11 + a20 * a21;
    float m02 = a00 * a02 + a10 * a12 + a20 * a22;
    float m11 = a01 * a01 + a11 * a11 + a21 * a21;
    float m12 = a01 * a02 + a11 * a12 + a21 * a22;
    float m22 = a02 * a02 + a12 * a12 + a22 * a22;

    float v00 = 1, v01 = 0, v02 = 0;
    float v10 = 0, v11 = 1, v12 = 0;
    float v20 = 0, v21 = 0, v22 = 1;

#pragma unroll 1
    for (int sweep = 0; sweep < 7; sweep++) {
        jrotf(m00, m11, m01, m02, m12, v00, v01, v10, v11, v20, v21);
        jrotf(m00, m22, m02, m01, m12, v00, v02, v10, v12, v20, v22);
        jrotf(m11, m22, m12, m01, m02, v01, v02, v11, v12, v21, v22);
    }

    float e0 = m00, e1 = m11, e2 = m22;
    int i1 = 0; float eb = e0;
    if (e1 > eb) { i1 = 1; eb = e1; }
    if (e2 > eb) { i1 = 2; eb = e2; }
    int i3 = 0; float es = e0;
    if (e1 < es) { i3 = 1; es = e1; }
    if (e2 < es) { i3 = 2; es = e2; }
    if (i3 == i1) i3 = (i1 + 1) % 3;
    int i2 = 3 - i1 - i3;

    float v1x = (i1 == 0) ? v00 : ((i1 == 1) ? v01 : v02);
    float v1y = (i1 == 0) ? v10 : ((i1 == 1) ? v11 : v12);
    float v1z = (i1 == 0) ? v20 : ((i1 == 1) ? v21 : v22);
    float v2x = (i2 == 0) ? v00 : ((i2 == 1) ? v01 : v02);
    float v2y = (i2 == 0) ? v10 : ((i2 == 1) ? v11 : v12);
    float v2z = (i2 == 0) ? v20 : ((i2 == 1) ? v21 : v22);

    float u1x = a00 * v1x + a01 * v1y + a02 * v1z;
    float u1y = a10 * v1x + a11 * v1y + a12 * v1z;
    float u1z = a20 * v1x + a21 * v1y + a22 * v1z;
    float n1 = sqrtf(u1x * u1x + u1y * u1y + u1z * u1z) + 1e-30f;
    float in1 = 1.f / n1;
    u1x *= in1; u1y *= in1; u1z *= in1;

    float u2x = a00 * v2x + a01 * v2y + a02 * v2z;
    float u2y = a10 * v2x + a11 * v2y + a12 * v2z;
    float u2z = a20 * v2x + a21 * v2y + a22 * v2z;
    float d12 = u1x * u2x + u1y * u2y + u1z * u2z;
    u2x -= d12 * u1x; u2y -= d12 * u1y; u2z -= d12 * u1z;
    float n2 = sqrtf(u2x * u2x + u2y * u2y + u2z * u2z) + 1e-30f;
    float in2 = 1.f / n2;
    u2x *= in2; u2y *= in2; u2z *= in2;

    float u3x = u1y * u2z - u1z * u2y;
    float u3y = u1z * u2x - u1x * u2z;
    float u3z = u1x * u2y - u1y * u2x;
    float w3x = v1y * v2z - v1z * v2y;
    float w3y = v1z * v2x - v1x * v2z;
    float w3z = v1x * v2y - v1y * v2x;

    float R[3][3];
    float U1[3] = { u1x, u1y, u1z }, U2[3] = { u2x, u2y, u2z }, U3[3] = { u3x, u3y, u3z };
    float V1[3] = { v1x, v1y, v1z }, V2[3] = { v2x, v2y, v2z }, W3[3] = { w3x, w3y, w3z };
#pragma unroll
    for (int i = 0; i < 3; i++)
#pragma unroll
        for (int j = 0; j < 3; j++) {
            R[i][j] = U1[i] * V1[j] + U2[i] * V2[j] + U3[i] * W3[j];
            outR[(size_t)n * 9 + 3 * i + j] = R[i][j];
        }

    float sc0 = g_srcc[n * 3 + 0], sc1 = g_srcc[n * 3 + 1], sc2 = g_srcc[n * 3 + 2];
    float tc0 = g_tgtc[n * 3 + 0], tc1 = g_tgtc[n * 3 + 1], tc2 = g_tgtc[n * 3 + 2];
    float t0 = tc0 - (R[0][0] * sc0 + R[0][1] * sc1 + R[0][2] * sc2);
    float t1 = tc1 - (R[1][0] * sc0 + R[1][1] * sc1 + R[1][2] * sc2);
    float t2 = tc2 - (R[2][0] * sc0 + R[2][1] * sc1 + R[2][2] * sc2);
    outT[(size_t)n * 3 + 0] = t0;
    outT[(size_t)n * 3 + 1] = t1;
    outT[(size_t)n * 3 + 2] = t2;

    // self-residual g(n) = |R*pos(n) + t - pred(n)|^2 (edge residual depends only on col)
    const float* pp = g_pp + (size_t)n * 6;
    float sx = pp[0], sy = pp[1], sz = pp[2];
    float px = pp[3], py = pp[4], pz = pp[5];
    float rx = R[0][0] * sx + R[0][1] * sy + R[0][2] * sz + t0 - px;
    float ry = R[1][0] * sx + R[1][1] * sy + R[1][2] * sz + t1 - py;
    float rz = R[2][0] * sx + R[2][1] * sy + R[2][2] * sz + t2 - pz;
    g_res[n] = rx * rx + ry * ry + rz * rz;
}

// ---------------- per-node dst = mean of neighbor residuals (4B gather) ----------------
__global__ void dst_kernel(const int* __restrict__ col, float* __restrict__ dst) {
    int node = (blockIdx.x * blockDim.x + threadIdx.x) >> 5;
    int lane = threadIdx.x & 31;
    if (node >= N_) return;
    float d = g_res[col[node * DEG + lane]];
#pragma unroll
    for (int o = 16; o; o >>= 1) d += __shfl_xor_sync(0xffffffffu, d, o);
    if (lane == 0) dst[node] = d * (1.f / (float)DEG);
}

// ---------------- launch ----------------
extern "C" void kernel_launch(void* const* d_in, const int* in_sizes, int n_in,
                              void* d_out, int out_size) {
    const float* S   = (const float*)d_in[0];
    const float* Tf  = (const float*)d_in[1];
    const float* TP  = (const float*)d_in[2];
    const float* pos = (const float*)d_in[3];
    const int*   ei  = (const int*)d_in[4];
    const int*   col = ei + (size_t)N_ * DEG;

    float* out   = (float*)d_out;
    float* outR  = out;
    float* outTr = out + (size_t)N_ * 9;
    float* outD  = out + (size_t)N_ * 12;

    cudaFuncSetAttribute(mma_topk_kernel, cudaFuncAttributeMaxDynamicSharedMemorySize, MAIN_SMEM);

    convS_kernel<<<(NROWPAD * F_ + 255) / 256, 256>>>(S, pos);
    convT_tn_kernel<<<(CTILEPAD * 32 + 255) / 256, 256>>>(Tf);
    mma_topk_kernel<<<RTILES * QSPLIT, 512, MAIN_SMEM>>>();
    rescore_kernel<<<(N_ * 32 + 255) / 256, 256>>>(S, Tf, TP);
    accum_kernel<<<(N_ * DEG + 255) / 256, 256>>>(col);
    svd_kernel<<<(N_ + 127) / 128, 128>>>(outR, outTr);
    dst_kernel<<<(N_ * DEG + 255) / 256, 256>>>(col, outD);
}